// round 1
// baseline (speedup 1.0000x reference)
#include <cuda_runtime.h>

#define NROWS 1024
#define MROWS 1024
#define DIM   512

// scratch: hx = x @ W1[:512], hy = y @ W1[512:]
__device__ float g_hx[NROWS * DIM];
__device__ float g_hy[MROWS * DIM];

typedef unsigned long long u64;

#define ADD2(d, a, b) \
    asm("add.rn.f32x2 %0, %1, %2;" : "=l"(d) : "l"(a), "l"(b))
#define FMA2(d, a, b, c) \
    asm("fma.rn.f32x2 %0, %1, %2, %3;" : "=l"(d) : "l"(a), "l"(b), "l"(c))

__device__ __forceinline__ u64 relu2(u64 s) {
    unsigned int lo, hi;
    asm("mov.b64 {%0,%1}, %2;" : "=r"(lo), "=r"(hi) : "l"(s));
    float f0 = fmaxf(__uint_as_float(lo), 0.0f);
    float f1 = fmaxf(__uint_as_float(hi), 0.0f);
    u64 r;
    asm("mov.b64 %0, {%1,%2};"
        : "=l"(r) : "r"(__float_as_uint(f0)), "r"(__float_as_uint(f1)));
    return r;
}

__device__ __forceinline__ float hsum2(u64 s) {
    unsigned int lo, hi;
    asm("mov.b64 {%0,%1}, %2;" : "=r"(lo), "=r"(hi) : "l"(s));
    return __uint_as_float(lo) + __uint_as_float(hi);
}

// -------------------------------------------------------------------------
// GEMM: C[m][n] = sum_k A[m][k] * W[k][n].  A: 1024x512, W: 512x512.
// z=0: A=x, W=W1[:512], C=g_hx ; z=1: A=y, W=W1[512:], C=g_hy
// 64x64 tile, BK=32, 256 threads, 4x4 per thread.
// -------------------------------------------------------------------------
__global__ void __launch_bounds__(256) gemm_dual(const float* __restrict__ x,
                                                 const float* __restrict__ y,
                                                 const float* __restrict__ W1) {
    const int z = blockIdx.z;
    const float* __restrict__ A = (z == 0) ? x : y;
    const float* __restrict__ W = W1 + z * DIM * DIM;
    float* __restrict__ C = (z == 0) ? g_hx : g_hy;

    __shared__ float As[32][68];   // [k][m], padded
    __shared__ float Bs[32][64];   // [k][n]

    const int tid = threadIdx.x;
    const int tn = tid & 15;
    const int tm = tid >> 4;
    const int m0 = blockIdx.y * 64;
    const int n0 = blockIdx.x * 64;

    float acc[4][4];
#pragma unroll
    for (int i = 0; i < 4; i++)
#pragma unroll
        for (int j = 0; j < 4; j++) acc[i][j] = 0.0f;

    for (int k0 = 0; k0 < DIM; k0 += 32) {
        // A tile, transposed into As[k][m]
#pragma unroll
        for (int it = 0; it < 2; it++) {
            int f = tid + it * 256;
            int r = f >> 3;       // m 0..63
            int c4 = f & 7;       // k/4 0..7
            float4 v = *(const float4*)&A[(m0 + r) * DIM + k0 + c4 * 4];
            As[c4 * 4 + 0][r] = v.x;
            As[c4 * 4 + 1][r] = v.y;
            As[c4 * 4 + 2][r] = v.z;
            As[c4 * 4 + 3][r] = v.w;
        }
        // W tile straight into Bs[k][n]
#pragma unroll
        for (int it = 0; it < 2; it++) {
            int f = tid + it * 256;
            int kr = f >> 4;      // 0..31
            int c4 = f & 15;      // 0..15
            *(float4*)&Bs[kr][c4 * 4] =
                *(const float4*)&W[(k0 + kr) * DIM + n0 + c4 * 4];
        }
        __syncthreads();

#pragma unroll
        for (int k = 0; k < 32; k++) {
            float4 a4 = *(const float4*)&As[k][tm * 4];
            float4 b4 = *(const float4*)&Bs[k][tn * 4];
            float av[4] = {a4.x, a4.y, a4.z, a4.w};
            float bv[4] = {b4.x, b4.y, b4.z, b4.w};
#pragma unroll
            for (int i = 0; i < 4; i++)
#pragma unroll
                for (int j = 0; j < 4; j++) acc[i][j] += av[i] * bv[j];
        }
        __syncthreads();
    }

#pragma unroll
    for (int i = 0; i < 4; i++) {
        float4 v = make_float4(acc[i][0], acc[i][1], acc[i][2], acc[i][3]);
        *(float4*)&C[(m0 + tm * 4 + i) * DIM + n0 + tn * 4] = v;
    }
}

// -------------------------------------------------------------------------
// Pairwise: out[i][j] = sum_d relu(hx[i][d] + hy[j][d]) * w2[d]
// 64x64 output tile per block, 256 threads, 4x4 per thread,
// d processed in chunks of 64, packed f32x2 along d.
// -------------------------------------------------------------------------
__global__ void __launch_bounds__(256) pairwise_kernel(const float* __restrict__ w2,
                                                       float* __restrict__ out) {
    __shared__ float xs[64][68];
    __shared__ float ys[64][68];
    __shared__ float w2s[64];

    const int tid = threadIdx.x;
    const int tx = tid & 15;   // j
    const int ty = tid >> 4;   // i
    const int i0 = blockIdx.y * 64;
    const int j0 = blockIdx.x * 64;

    u64 acc[4][4];
#pragma unroll
    for (int i = 0; i < 4; i++)
#pragma unroll
        for (int j = 0; j < 4; j++) acc[i][j] = 0ULL;  // (0.f, 0.f)

    for (int d0 = 0; d0 < DIM; d0 += 64) {
#pragma unroll
        for (int it = 0; it < 4; it++) {
            int f = tid + it * 256;
            int r = f >> 4;    // 0..63
            int c = f & 15;    // 0..15
            *(float4*)&xs[r][c * 4] =
                *(const float4*)&g_hx[(i0 + r) * DIM + d0 + c * 4];
            *(float4*)&ys[r][c * 4] =
                *(const float4*)&g_hy[(j0 + r) * DIM + d0 + c * 4];
        }
        if (tid < 16)
            *(float4*)&w2s[tid * 4] = *(const float4*)&w2[d0 + tid * 4];
        __syncthreads();

#pragma unroll 2
        for (int dd = 0; dd < 64; dd += 4) {
            u64 a[4][2], b[4][2];
#pragma unroll
            for (int ti = 0; ti < 4; ti++) {
                ulonglong2 av = *(const ulonglong2*)&xs[ty * 4 + ti][dd];
                a[ti][0] = av.x;
                a[ti][1] = av.y;
            }
#pragma unroll
            for (int tj = 0; tj < 4; tj++) {
                ulonglong2 bv = *(const ulonglong2*)&ys[tx * 4 + tj][dd];
                b[tj][0] = bv.x;
                b[tj][1] = bv.y;
            }
            ulonglong2 wv = *(const ulonglong2*)&w2s[dd];
            u64 w[2];
            w[0] = wv.x;
            w[1] = wv.y;
#pragma unroll
            for (int ti = 0; ti < 4; ti++)
#pragma unroll
                for (int tj = 0; tj < 4; tj++) {
#pragma unroll
                    for (int p = 0; p < 2; p++) {
                        u64 s;
                        ADD2(s, a[ti][p], b[tj][p]);
                        s = relu2(s);
                        FMA2(acc[ti][tj], s, w[p], acc[ti][tj]);
                    }
                }
        }
        __syncthreads();
    }

#pragma unroll
    for (int ti = 0; ti < 4; ti++) {
        float4 o;
        o.x = hsum2(acc[ti][0]);
        o.y = hsum2(acc[ti][1]);
        o.z = hsum2(acc[ti][2]);
        o.w = hsum2(acc[ti][3]);
        *(float4*)&out[(i0 + ty * 4 + ti) * MROWS + j0 + tx * 4] = o;
    }
}

extern "C" void kernel_launch(void* const* d_in, const int* in_sizes, int n_in,
                              void* d_out, int out_size) {
    const float* x  = (const float*)d_in[0];
    const float* y  = (const float*)d_in[1];
    const float* W1 = (const float*)d_in[2];
    const float* W2 = (const float*)d_in[3];
    float* out = (float*)d_out;

    dim3 ggrid(DIM / 64, NROWS / 64, 2);   // (8, 16, 2)
    gemm_dual<<<ggrid, 256>>>(x, y, W1);

    dim3 pgrid(MROWS / 64, NROWS / 64);    // (16, 16)
    pairwise_kernel<<<pgrid, 256>>>(W2, out);
}

// round 3
// speedup vs baseline: 1.1923x; 1.1923x over previous
#include <cuda_runtime.h>

#define NROWS 1024
#define MROWS 1024
#define DIM   512
#define DHALF 256

// scratch: hx = x @ W1[:512], hy = y @ W1[512:]
__device__ float g_hx[NROWS * DIM];
__device__ float g_hy[MROWS * DIM];
// pairwise partial sums, one buffer per d-half
__device__ float g_part[2 * NROWS * MROWS];

typedef unsigned long long u64;

#define ADD2(d, a, b) \
    asm("add.rn.f32x2 %0, %1, %2;" : "=l"(d) : "l"(a), "l"(b))
#define FMA2(d, a, b, c) \
    asm("fma.rn.f32x2 %0, %1, %2, %3;" : "=l"(d) : "l"(a), "l"(b), "l"(c))

__device__ __forceinline__ u64 relu2(u64 s) {
    unsigned int lo, hi;
    asm("mov.b64 {%0,%1}, %2;" : "=r"(lo), "=r"(hi) : "l"(s));
    float f0 = fmaxf(__uint_as_float(lo), 0.0f);
    float f1 = fmaxf(__uint_as_float(hi), 0.0f);
    u64 r;
    asm("mov.b64 %0, {%1,%2};"
        : "=l"(r) : "r"(__float_as_uint(f0)), "r"(__float_as_uint(f1)));
    return r;
}

__device__ __forceinline__ float hsum2(u64 s) {
    unsigned int lo, hi;
    asm("mov.b64 {%0,%1}, %2;" : "=r"(lo), "=r"(hi) : "l"(s));
    return __uint_as_float(lo) + __uint_as_float(hi);
}

// -------------------------------------------------------------------------
// GEMM (f32x2-packed over k): C[m][n] = sum_k A[m][k] * W[k][n].
// z=0: A=x, W=W1[:512], C=g_hx ; z=1: A=y, W=W1[512:], C=g_hy
// 64x64 tile, BK=32, 256 threads, 4x4 per thread.
// Smem layouts are k-contiguous: As[m][k], Bs[n][k], row stride 36 words
// (16B aligned, odd granule -> conflict-free for the strided-row b loads).
// -------------------------------------------------------------------------
__global__ void __launch_bounds__(256) gemm_dual(const float* __restrict__ x,
                                                 const float* __restrict__ y,
                                                 const float* __restrict__ W1) {
    const int z = blockIdx.z;
    const float* __restrict__ A = (z == 0) ? x : y;
    const float* __restrict__ W = W1 + z * DIM * DIM;
    float* __restrict__ C = (z == 0) ? g_hx : g_hy;

    __shared__ float As[64][36];   // [m][k]
    __shared__ float Bs[64][36];   // [n][k]

    const int tid = threadIdx.x;
    const int tn = tid & 15;
    const int tm = tid >> 4;
    const int m0 = blockIdx.y * 64;
    const int n0 = blockIdx.x * 64;

    u64 acc[4][4];
#pragma unroll
    for (int i = 0; i < 4; i++)
#pragma unroll
        for (int j = 0; j < 4; j++) acc[i][j] = 0ULL;

    for (int k0 = 0; k0 < DIM; k0 += 32) {
        // A tile: direct copy, k-contiguous rows
#pragma unroll
        for (int it = 0; it < 2; it++) {
            int f = tid + it * 256;
            int r = f >> 3;       // m 0..63
            int c4 = f & 7;       // k/4
            *(float4*)&As[r][c4 * 4] =
                *(const float4*)&A[(m0 + r) * DIM + k0 + c4 * 4];
        }
        // W tile: transpose [k][n] -> Bs[n][k]
#pragma unroll
        for (int it = 0; it < 2; it++) {
            int f = tid + it * 256;
            int kr = f & 31;      // k 0..31 (warp covers all 32 -> STS conflict-free)
            int c4 = f >> 5;      // n/4 0..15
            float4 v = *(const float4*)&W[(k0 + kr) * DIM + n0 + c4 * 4];
            Bs[c4 * 4 + 0][kr] = v.x;
            Bs[c4 * 4 + 1][kr] = v.y;
            Bs[c4 * 4 + 2][kr] = v.z;
            Bs[c4 * 4 + 3][kr] = v.w;
        }
        __syncthreads();

#pragma unroll
        for (int kk = 0; kk < 32; kk += 2) {
            u64 a2[4], b2[4];
#pragma unroll
            for (int i = 0; i < 4; i++)
                a2[i] = *(const u64*)&As[tm * 4 + i][kk];
#pragma unroll
            for (int j = 0; j < 4; j++)
                b2[j] = *(const u64*)&Bs[tn + 16 * j][kk];
#pragma unroll
            for (int i = 0; i < 4; i++)
#pragma unroll
                for (int j = 0; j < 4; j++)
                    FMA2(acc[i][j], a2[i], b2[j], acc[i][j]);
        }
        __syncthreads();
    }

#pragma unroll
    for (int i = 0; i < 4; i++)
#pragma unroll
        for (int j = 0; j < 4; j++)
            C[(m0 + tm * 4 + i) * DIM + n0 + tn + 16 * j] = hsum2(acc[i][j]);
}

// -------------------------------------------------------------------------
// Pairwise: part[z][i][j] = sum_{d in half z} relu(hx[i][d]+hy[j][d])*w2[d]
// 64x64 output tile, 256 threads, 4x4 per thread with STRIDED row mapping
// (i = ty + 16*ti, j = tx + 16*tj) -> conflict-free ys loads.
// grid.z = 2 d-halves -> 512 blocks for occupancy.
// -------------------------------------------------------------------------
__global__ void __launch_bounds__(256) pairwise_kernel(const float* __restrict__ w2) {
    __shared__ float xs[64][68];
    __shared__ float ys[64][68];
    __shared__ float w2s[64];

    const int tid = threadIdx.x;
    const int tx = tid & 15;   // j base
    const int ty = tid >> 4;   // i base
    const int i0 = blockIdx.y * 64;
    const int j0 = blockIdx.x * 64;
    const int z  = blockIdx.z;
    const int dbase = z * DHALF;

    u64 acc[4][4];
#pragma unroll
    for (int i = 0; i < 4; i++)
#pragma unroll
        for (int j = 0; j < 4; j++) acc[i][j] = 0ULL;

    for (int d0 = 0; d0 < DHALF; d0 += 64) {
        const int dg = dbase + d0;
#pragma unroll
        for (int it = 0; it < 4; it++) {
            int f = tid + it * 256;
            int r = f >> 4;    // 0..63
            int c = f & 15;    // 0..15
            *(float4*)&xs[r][c * 4] =
                *(const float4*)&g_hx[(i0 + r) * DIM + dg + c * 4];
            *(float4*)&ys[r][c * 4] =
                *(const float4*)&g_hy[(j0 + r) * DIM + dg + c * 4];
        }
        if (tid < 16)
            *(float4*)&w2s[tid * 4] = *(const float4*)&w2[dg + tid * 4];
        __syncthreads();

#pragma unroll 2
        for (int dd = 0; dd < 64; dd += 4) {
            u64 a[4][2], b[4][2];
#pragma unroll
            for (int ti = 0; ti < 4; ti++) {
                ulonglong2 av = *(const ulonglong2*)&xs[ty + 16 * ti][dd];
                a[ti][0] = av.x;
                a[ti][1] = av.y;
            }
#pragma unroll
            for (int tj = 0; tj < 4; tj++) {
                ulonglong2 bv = *(const ulonglong2*)&ys[tx + 16 * tj][dd];
                b[tj][0] = bv.x;
                b[tj][1] = bv.y;
            }
            ulonglong2 wv = *(const ulonglong2*)&w2s[dd];
            u64 w[2];
            w[0] = wv.x;
            w[1] = wv.y;
#pragma unroll
            for (int ti = 0; ti < 4; ti++)
#pragma unroll
                for (int tj = 0; tj < 4; tj++) {
#pragma unroll
                    for (int p = 0; p < 2; p++) {
                        u64 s;
                        ADD2(s, a[ti][p], b[tj][p]);
                        s = relu2(s);
                        FMA2(acc[ti][tj], s, w[p], acc[ti][tj]);
                    }
                }
        }
        __syncthreads();
    }

    float* __restrict__ part = g_part + z * (NROWS * MROWS);
#pragma unroll
    for (int ti = 0; ti < 4; ti++)
#pragma unroll
        for (int tj = 0; tj < 4; tj++)
            part[(i0 + ty + 16 * ti) * MROWS + j0 + tx + 16 * tj] =
                hsum2(acc[ti][tj]);
}

// out = part0 + part1
__global__ void __launch_bounds__(256) reduce_add(float* __restrict__ out) {
    int idx = (blockIdx.x * 256 + threadIdx.x) * 4;
    float4 a = *(const float4*)&g_part[idx];
    float4 b = *(const float4*)&g_part[NROWS * MROWS + idx];
    float4 o;
    o.x = a.x + b.x;
    o.y = a.y + b.y;
    o.z = a.z + b.z;
    o.w = a.w + b.w;
    *(float4*)&out[idx] = o;
}

extern "C" void kernel_launch(void* const* d_in, const int* in_sizes, int n_in,
                              void* d_out, int out_size) {
    const float* x  = (const float*)d_in[0];
    const float* y  = (const float*)d_in[1];
    const float* W1 = (const float*)d_in[2];
    const float* W2 = (const float*)d_in[3];
    float* out = (float*)d_out;

    dim3 ggrid(DIM / 64, NROWS / 64, 2);     // (8, 16, 2)
    gemm_dual<<<ggrid, 256>>>(x, y, W1);

    dim3 pgrid(MROWS / 64, NROWS / 64, 2);   // (16, 16, 2)
    pairwise_kernel<<<pgrid, 256>>>(W2);

    reduce_add<<<(NROWS * MROWS) / 1024, 256>>>(out);
}

// round 4
// speedup vs baseline: 1.2691x; 1.0644x over previous
#include <cuda_runtime.h>

#define NROWS 1024
#define MROWS 1024
#define DIM   512
#define DHALF 256

__device__ float g_hx[NROWS * DIM];
__device__ float g_hy[MROWS * DIM];
__device__ float g_part[2 * NROWS * MROWS];

typedef unsigned long long u64;

#define ADD2(d, a, b) \
    asm("add.rn.f32x2 %0, %1, %2;" : "=l"(d) : "l"(a), "l"(b))
#define FMA2(d, a, b, c) \
    asm("fma.rn.f32x2 %0, %1, %2, %3;" : "=l"(d) : "l"(a), "l"(b), "l"(c))

__device__ __forceinline__ u64 relu2(u64 s) {
    unsigned int lo, hi;
    asm("mov.b64 {%0,%1}, %2;" : "=r"(lo), "=r"(hi) : "l"(s));
    float f0 = fmaxf(__uint_as_float(lo), 0.0f);
    float f1 = fmaxf(__uint_as_float(hi), 0.0f);
    u64 r;
    asm("mov.b64 %0, {%1,%2};"
        : "=l"(r) : "r"(__float_as_uint(f0)), "r"(__float_as_uint(f1)));
    return r;
}

__device__ __forceinline__ float hsum2(u64 s) {
    unsigned int lo, hi;
    asm("mov.b64 {%0,%1}, %2;" : "=r"(lo), "=r"(hi) : "l"(s));
    return __uint_as_float(lo) + __uint_as_float(hi);
}

// -------------------------------------------------------------------------
// GEMM, double-buffered. C[m][n] = sum_k A[m][k]*W[k][n].
// As stride 36 (a-loads broadcast, float4-aligned stores).
// Bs stride 34 (34 mod 32 = 2 -> 16 consumer rows hit 16 distinct banks:
//               conflict-free LDS.64; 136B rows stay 8B-aligned).
// -------------------------------------------------------------------------
__global__ void __launch_bounds__(256) gemm_dual(const float* __restrict__ x,
                                                 const float* __restrict__ y,
                                                 const float* __restrict__ W1) {
    const int z = blockIdx.z;
    const float* __restrict__ A = (z == 0) ? x : y;
    const float* __restrict__ W = W1 + z * DIM * DIM;
    float* __restrict__ C = (z == 0) ? g_hx : g_hy;

    __shared__ float As[2][64][36];
    __shared__ float Bs[2][64][34];

    const int tid = threadIdx.x;
    const int tn = tid & 15;
    const int tm = tid >> 4;
    const int m0 = blockIdx.y * 64;
    const int n0 = blockIdx.x * 64;

    // loader maps
    const int ar = tid >> 3;     // A row base (0..31), +32 for it=1
    const int ac = tid & 7;      // A col4
    const int wk = tid >> 4;     // W k-row base (0..15), +16 for it=1
    const int wc = tid & 15;     // W col4

    u64 acc[4][4];
#pragma unroll
    for (int i = 0; i < 4; i++)
#pragma unroll
        for (int j = 0; j < 4; j++) acc[i][j] = 0ULL;

    float4 aS[2], wS[2];
    // prefetch k0 = 0
#pragma unroll
    for (int it = 0; it < 2; it++) {
        aS[it] = *(const float4*)&A[(m0 + ar + it * 32) * DIM + ac * 4];
        wS[it] = *(const float4*)&W[(wk + it * 16) * DIM + n0 + wc * 4];
    }
#pragma unroll
    for (int it = 0; it < 2; it++) {
        *(float4*)&As[0][ar + it * 32][ac * 4] = aS[it];
        Bs[0][wc * 4 + 0][wk + it * 16] = wS[it].x;
        Bs[0][wc * 4 + 1][wk + it * 16] = wS[it].y;
        Bs[0][wc * 4 + 2][wk + it * 16] = wS[it].z;
        Bs[0][wc * 4 + 3][wk + it * 16] = wS[it].w;
    }
    __syncthreads();

#pragma unroll 2
    for (int k0i = 0; k0i < 16; k0i++) {
        const int buf = k0i & 1;
        if (k0i < 15) {
            const int kng = (k0i + 1) * 32;
#pragma unroll
            for (int it = 0; it < 2; it++) {
                aS[it] = *(const float4*)&A[(m0 + ar + it * 32) * DIM + kng + ac * 4];
                wS[it] = *(const float4*)&W[(kng + wk + it * 16) * DIM + n0 + wc * 4];
            }
        }

#pragma unroll
        for (int kk = 0; kk < 32; kk += 2) {
            u64 a2[4], b2[4];
#pragma unroll
            for (int i = 0; i < 4; i++)
                a2[i] = *(const u64*)&As[buf][tm * 4 + i][kk];
#pragma unroll
            for (int j = 0; j < 4; j++)
                b2[j] = *(const u64*)&Bs[buf][tn + 16 * j][kk];
#pragma unroll
            for (int i = 0; i < 4; i++)
#pragma unroll
                for (int j = 0; j < 4; j++)
                    FMA2(acc[i][j], a2[i], b2[j], acc[i][j]);
        }

        if (k0i < 15) {
            const int nb = buf ^ 1;
#pragma unroll
            for (int it = 0; it < 2; it++) {
                *(float4*)&As[nb][ar + it * 32][ac * 4] = aS[it];
                Bs[nb][wc * 4 + 0][wk + it * 16] = wS[it].x;
                Bs[nb][wc * 4 + 1][wk + it * 16] = wS[it].y;
                Bs[nb][wc * 4 + 2][wk + it * 16] = wS[it].z;
                Bs[nb][wc * 4 + 3][wk + it * 16] = wS[it].w;
            }
        }
        __syncthreads();
    }

#pragma unroll
    for (int i = 0; i < 4; i++)
#pragma unroll
        for (int j = 0; j < 4; j++)
            C[(m0 + tm * 4 + i) * DIM + n0 + tn + 16 * j] = hsum2(acc[i][j]);
}

// -------------------------------------------------------------------------
// Pairwise: part[z][i][j] = sum_{d in half z} relu(hx[i][d]+hy[j][d])*w2[d]
// Strided row mapping (conflict-optimal), launch_bounds(256,3) -> 24 warps/SM.
// -------------------------------------------------------------------------
__global__ void __launch_bounds__(256, 3) pairwise_kernel(const float* __restrict__ w2) {
    __shared__ float xs[64][68];
    __shared__ float ys[64][68];
    __shared__ float w2s[64];

    const int tid = threadIdx.x;
    const int tx = tid & 15;
    const int ty = tid >> 4;
    const int i0 = blockIdx.y * 64;
    const int j0 = blockIdx.x * 64;
    const int z  = blockIdx.z;
    const int dbase = z * DHALF;

    u64 acc[4][4];
#pragma unroll
    for (int i = 0; i < 4; i++)
#pragma unroll
        for (int j = 0; j < 4; j++) acc[i][j] = 0ULL;

    for (int d0 = 0; d0 < DHALF; d0 += 64) {
        const int dg = dbase + d0;
#pragma unroll
        for (int it = 0; it < 4; it++) {
            int f = tid + it * 256;
            int r = f >> 4;
            int c = f & 15;
            *(float4*)&xs[r][c * 4] =
                *(const float4*)&g_hx[(i0 + r) * DIM + dg + c * 4];
            *(float4*)&ys[r][c * 4] =
                *(const float4*)&g_hy[(j0 + r) * DIM + dg + c * 4];
        }
        if (tid < 16)
            *(float4*)&w2s[tid * 4] = *(const float4*)&w2[dg + tid * 4];
        __syncthreads();

#pragma unroll 2
        for (int dd = 0; dd < 64; dd += 4) {
            u64 a[4][2], b[4][2];
#pragma unroll
            for (int ti = 0; ti < 4; ti++) {
                ulonglong2 av = *(const ulonglong2*)&xs[ty + 16 * ti][dd];
                a[ti][0] = av.x;
                a[ti][1] = av.y;
            }
#pragma unroll
            for (int tj = 0; tj < 4; tj++) {
                ulonglong2 bv = *(const ulonglong2*)&ys[tx + 16 * tj][dd];
                b[tj][0] = bv.x;
                b[tj][1] = bv.y;
            }
            ulonglong2 wv = *(const ulonglong2*)&w2s[dd];
            u64 w[2];
            w[0] = wv.x;
            w[1] = wv.y;
#pragma unroll
            for (int ti = 0; ti < 4; ti++)
#pragma unroll
                for (int tj = 0; tj < 4; tj++) {
#pragma unroll
                    for (int p = 0; p < 2; p++) {
                        u64 s;
                        ADD2(s, a[ti][p], b[tj][p]);
                        s = relu2(s);
                        FMA2(acc[ti][tj], s, w[p], acc[ti][tj]);
                    }
                }
        }
        __syncthreads();
    }

    float* __restrict__ part = g_part + z * (NROWS * MROWS);
#pragma unroll
    for (int ti = 0; ti < 4; ti++)
#pragma unroll
        for (int tj = 0; tj < 4; tj++)
            part[(i0 + ty + 16 * ti) * MROWS + j0 + tx + 16 * tj] =
                hsum2(acc[ti][tj]);
}

__global__ void __launch_bounds__(256) reduce_add(float* __restrict__ out) {
    int idx = (blockIdx.x * 256 + threadIdx.x) * 4;
    float4 a = *(const float4*)&g_part[idx];
    float4 b = *(const float4*)&g_part[NROWS * MROWS + idx];
    float4 o;
    o.x = a.x + b.x;
    o.y = a.y + b.y;
    o.z = a.z + b.z;
    o.w = a.w + b.w;
    *(float4*)&out[idx] = o;
}

extern "C" void kernel_launch(void* const* d_in, const int* in_sizes, int n_in,
                              void* d_out, int out_size) {
    const float* x  = (const float*)d_in[0];
    const float* y  = (const float*)d_in[1];
    const float* W1 = (const float*)d_in[2];
    const float* W2 = (const float*)d_in[3];
    float* out = (float*)d_out;

    dim3 ggrid(DIM / 64, NROWS / 64, 2);
    gemm_dual<<<ggrid, 256>>>(x, y, W1);

    dim3 pgrid(MROWS / 64, NROWS / 64, 2);
    pairwise_kernel<<<pgrid, 256>>>(W2);

    reduce_add<<<(NROWS * MROWS) / 1024, 256>>>(out);
}